// round 9
// baseline (speedup 1.0000x reference)
#include <cuda_runtime.h>

// Problem constants
#define T_  4
#define B_  16
#define C_  512
#define N_  1024
#define CR_ 64
#define TB_ (T_ * B_)          // 64
#define BN_EPS 1e-5f

// Scratch (allocation-free rule: __device__ globals)
__device__ float g_gap[TB_ * C_];   // [64, 512]
__device__ float g_h1[TB_ * CR_];   // [64, 64]

// Software grid barrier (generation counter survives graph replays:
// count returns to 0 each use; gen increases monotonically -> deterministic).
__device__ unsigned g_bar_count = 0;
__device__ volatile unsigned g_bar_gen = 0;

// ---------------------------------------------------------------------------
// K1: LIF over T=4 + GAP over N, fused. One block per (b, c): 8192 blocks.
// 256 threads, each owns one float4 per timestep (front-batched, MLP_p1=4).
// Streaming loads (__ldcs): x is touched exactly once.
// Blocks 0..7 prefetch w1/w2 into L2 for the MLP kernel.
// ---------------------------------------------------------------------------
__global__ void __launch_bounds__(256) lif_gap_kernel(const float* __restrict__ x,
                                                      const float* __restrict__ w1,
                                                      const float* __restrict__ w2,
                                                      float* __restrict__ g) {
    const int bc  = blockIdx.x;          // 0..8191
    const int b   = bc >> 9;             // /512
    const int c   = bc & (C_ - 1);
    const int tid = threadIdx.x;

    if (bc < 8) {
        const float* wsrc = (bc < 4) ? w1 : w2;
        const char* line = (const char*)wsrc + ((size_t)(bc & 3) * 256 + tid) * 128;
        asm volatile("prefetch.global.L2 [%0];" :: "l"(line));
    }

    const size_t strideT = (size_t)B_ * C_ * N_;
    const size_t base = ((size_t)b * C_ + c) * N_ + (size_t)tid * 4;

    float4 xt[T_];
#pragma unroll
    for (int t = 0; t < T_; t++)
        xt[t] = __ldcs(reinterpret_cast<const float4*>(x + base + (size_t)t * strideT));

    float sums[T_] = {0.f, 0.f, 0.f, 0.f};
#pragma unroll
    for (int slot = 0; slot < 4; slot++) {
        float v = 0.f;
#pragma unroll
        for (int t = 0; t < T_; t++) {
            float xv = (slot == 0) ? xt[t].x : (slot == 1) ? xt[t].y
                     : (slot == 2) ? xt[t].z : xt[t].w;
            v = 0.5f * (v + xv);                 // v += (x - v)/TAU, TAU=2
            float s = (v >= 1.0f) ? 1.0f : 0.0f; // spike(v - V_TH)
            sums[t] += s;
            v *= (1.0f - s);                     // hard reset (detached)
        }
    }

    __shared__ float red[8][T_];
    const int lane = tid & 31;
    const int wid  = tid >> 5;
#pragma unroll
    for (int t = 0; t < T_; t++) {
#pragma unroll
        for (int off = 16; off > 0; off >>= 1)
            sums[t] += __shfl_xor_sync(0xFFFFFFFFu, sums[t], off);
    }
    if (lane == 0) {
#pragma unroll
        for (int t = 0; t < T_; t++) red[wid][t] = sums[t];
    }
    __syncthreads();

    if (tid < T_) {
        float tot = 0.f;
#pragma unroll
        for (int w = 0; w < 8; w++) tot += red[w][tid];
        g[((tid * B_ + b) * C_) + c] = tot * (1.0f / (float)N_);
    }
}

// ---------------------------------------------------------------------------
// K2: full MLP, fused, ILP-maximized. 64 blocks x 256 threads, co-resident.
// Phase 1 (block j): h1[:, j] = BN1(g @ w1[j,:] + b1[j]).
//   Each warp: 8 rows with 8 INDEPENDENT accumulators; all 32 g-loads
//   front-batched; 8 shuffle-reduce chains interleaved.
// Grid barrier (pure spin).
// Phase 2 (block j): 8 FC2 columns; both reps' loads issued up front.
// ---------------------------------------------------------------------------
__global__ void __launch_bounds__(256) mlp_fused_kernel(const float* __restrict__ g,
                                                        const float* __restrict__ w1,
                                                        const float* __restrict__ b1,
                                                        const float* __restrict__ gamma1,
                                                        const float* __restrict__ beta1,
                                                        const float* __restrict__ w2,
                                                        const float* __restrict__ b2,
                                                        const float* __restrict__ gamma2,
                                                        const float* __restrict__ beta2,
                                                        float* __restrict__ h1,
                                                        float* __restrict__ out) {
    const int j   = blockIdx.x;   // 0..63
    const int tid = threadIdx.x;

    __shared__ float4 w1s[C_ / 4];     // 2 KB
    __shared__ float  hrow[TB_];
    __shared__ float  ss[4][2], sq[4][2];

    // Stage w1 row j (coalesced, 128 threads)
    if (tid < C_ / 4)
        w1s[tid] = reinterpret_cast<const float4*>(w1 + (size_t)j * C_)[tid];
    __syncthreads();

    // ---------------- Phase 1 ----------------
    {
        const int w = tid >> 5, l = tid & 31;
        const float4* g4 = reinterpret_cast<const float4*>(g);
        float acc[8] = {0.f,0.f,0.f,0.f,0.f,0.f,0.f,0.f};
        // All loads independent: 4 chunks x 8 rows, front-batched by ptxas
#pragma unroll
        for (int s = 0; s < 4; s++) {
            float4 wv = w1s[l + s * 32];
#pragma unroll
            for (int r = 0; r < 8; r++) {
                const int i = w * 8 + r;                     // batch row
                float4 a = g4[(size_t)i * (C_ / 4) + l + s * 32];
                acc[r] += a.x * wv.x + a.y * wv.y + a.z * wv.z + a.w * wv.w;
            }
        }
        // 8 interleaved shuffle-reduce chains
#pragma unroll
        for (int off = 16; off > 0; off >>= 1)
#pragma unroll
            for (int r = 0; r < 8; r++)
                acc[r] += __shfl_xor_sync(0xFFFFFFFFu, acc[r], off);
        if (l == 0) {
#pragma unroll
            for (int r = 0; r < 8; r++) hrow[w * 8 + r] = acc[r] + b1[j];
        }
    }
    __syncthreads();

    // BN1 column stats (64 values, 2 warps)
    if (tid < TB_) {
        float h = hrow[tid];
        float s = h, q = h * h;
#pragma unroll
        for (int off = 16; off > 0; off >>= 1) {
            s += __shfl_xor_sync(0xFFFFFFFFu, s, off);
            q += __shfl_xor_sync(0xFFFFFFFFu, q, off);
        }
        if ((tid & 31) == 0) { ss[0][tid >> 5] = s; sq[0][tid >> 5] = q; }
    }
    __syncthreads();
    if (tid < TB_) {
        float mu  = (ss[0][0] + ss[0][1]) * (1.0f / (float)TB_);
        float ex2 = (sq[0][0] + sq[0][1]) * (1.0f / (float)TB_);
        float var = ex2 - mu * mu;
        h1[tid * CR_ + j] = (hrow[tid] - mu) * rsqrtf(var + BN_EPS) * gamma1[j] + beta1[j];
    }
    __syncthreads();

    // ---------------- Grid barrier (64 co-resident blocks) ----------------
    if (tid == 0) {
        __threadfence();                               // publish h1
        unsigned gen = g_bar_gen;
        unsigned old = atomicAdd(&g_bar_count, 1);
        if (old == (unsigned)(gridDim.x - 1)) {
            g_bar_count = 0;
            __threadfence();
            g_bar_gen = gen + 1;                       // release
        } else {
            while (g_bar_gen == gen) { }               // tight spin (~L2 poll)
        }
    }
    __syncthreads();
    __threadfence();                                   // acquire h1

    // ---------------- Phase 2: out[:, j*8 .. j*8+7] ----------------
    {
        const int grp = tid >> 6;         // 0..3
        const int gt  = tid & 63;         // batch row
        const int gw  = (tid >> 5) & 1;   // warp within group
        const int jj0 = j * 8 + grp;
        const int jj1 = j * 8 + 4 + grp;

        const float4* hr  = reinterpret_cast<const float4*>(h1 + (size_t)gt * CR_);
        const float4* wr0 = reinterpret_cast<const float4*>(w2 + (size_t)jj0 * CR_);
        const float4* wr1 = reinterpret_cast<const float4*>(w2 + (size_t)jj1 * CR_);

        float a00=0.f, a01=0.f, a02=0.f, a03=0.f;
        float a10=0.f, a11=0.f, a12=0.f, a13=0.f;
#pragma unroll
        for (int k = 0; k < CR_ / 16; k++) {
            float4 x0 = hr[k*4+0], x1 = hr[k*4+1], x2 = hr[k*4+2], x3 = hr[k*4+3];
            float4 u0 = wr0[k*4+0], u1 = wr0[k*4+1], u2 = wr0[k*4+2], u3 = wr0[k*4+3];
            float4 v0 = wr1[k*4+0], v1 = wr1[k*4+1], v2 = wr1[k*4+2], v3 = wr1[k*4+3];
            a00 += x0.x*u0.x + x0.y*u0.y + x0.z*u0.z + x0.w*u0.w;
            a01 += x1.x*u1.x + x1.y*u1.y + x1.z*u1.z + x1.w*u1.w;
            a02 += x2.x*u2.x + x2.y*u2.y + x2.z*u2.z + x2.w*u2.w;
            a03 += x3.x*u3.x + x3.y*u3.y + x3.z*u3.z + x3.w*u3.w;
            a10 += x0.x*v0.x + x0.y*v0.y + x0.z*v0.z + x0.w*v0.w;
            a11 += x1.x*v1.x + x1.y*v1.y + x1.z*v1.z + x1.w*v1.w;
            a12 += x2.x*v2.x + x2.y*v2.y + x2.z*v2.z + x2.w*v2.w;
            a13 += x3.x*v3.x + x3.y*v3.y + x3.z*v3.z + x3.w*v3.w;
        }
        float h0 = (a00 + a01) + (a02 + a03) + b2[jj0];
        float h1v = (a10 + a11) + (a12 + a13) + b2[jj1];

        // Two interleaved stat reductions over the 64-thread group
        float s0 = h0, q0 = h0 * h0, s1 = h1v, q1 = h1v * h1v;
#pragma unroll
        for (int off = 16; off > 0; off >>= 1) {
            s0 += __shfl_xor_sync(0xFFFFFFFFu, s0, off);
            q0 += __shfl_xor_sync(0xFFFFFFFFu, q0, off);
            s1 += __shfl_xor_sync(0xFFFFFFFFu, s1, off);
            q1 += __shfl_xor_sync(0xFFFFFFFFu, q1, off);
        }
        __shared__ float ss1[4][2], sq1[4][2];
        if ((gt & 31) == 0) {
            ss[grp][gw] = s0;  sq[grp][gw] = q0;
            ss1[grp][gw] = s1; sq1[grp][gw] = q1;
        }
        __syncthreads();
        {
            float mu  = (ss[grp][0] + ss[grp][1]) * (1.0f / (float)TB_);
            float ex2 = (sq[grp][0] + sq[grp][1]) * (1.0f / (float)TB_);
            float var = ex2 - mu * mu;
            out[gt * C_ + jj0] = (h0 - mu) * rsqrtf(var + BN_EPS) * gamma2[jj0] + beta2[jj0];
        }
        {
            float mu  = (ss1[grp][0] + ss1[grp][1]) * (1.0f / (float)TB_);
            float ex2 = (sq1[grp][0] + sq1[grp][1]) * (1.0f / (float)TB_);
            float var = ex2 - mu * mu;
            out[gt * C_ + jj1] = (h1v - mu) * rsqrtf(var + BN_EPS) * gamma2[jj1] + beta2[jj1];
        }
    }
}

// ---------------------------------------------------------------------------
extern "C" void kernel_launch(void* const* d_in, const int* in_sizes, int n_in,
                              void* d_out, int out_size) {
    const float* x      = (const float*)d_in[0];
    const float* w1     = (const float*)d_in[1];
    const float* b1     = (const float*)d_in[2];
    const float* gamma1 = (const float*)d_in[3];
    const float* beta1  = (const float*)d_in[4];
    const float* w2     = (const float*)d_in[5];
    const float* b2     = (const float*)d_in[6];
    const float* gamma2 = (const float*)d_in[7];
    const float* beta2  = (const float*)d_in[8];
    float* out = (float*)d_out;

    float* g;  cudaGetSymbolAddress((void**)&g,  g_gap);
    float* h1; cudaGetSymbolAddress((void**)&h1, g_h1);

    lif_gap_kernel<<<B_ * C_, 256>>>(x, w1, w2, g);
    mlp_fused_kernel<<<CR_, 256>>>(g, w1, b1, gamma1, beta1,
                                   w2, b2, gamma2, beta2, h1, out);
}

// round 10
// speedup vs baseline: 1.0596x; 1.0596x over previous
#include <cuda_runtime.h>

// Problem constants
#define T_  4
#define B_  16
#define C_  512
#define N_  1024
#define CR_ 64
#define TB_ (T_ * B_)          // 64
#define BN_EPS 1e-5f

// Scratch (allocation-free rule: __device__ globals)
__device__ float g_gap[TB_ * C_];   // [64, 512]
__device__ float g_h1[TB_ * CR_];   // [64, 64]

// Software grid barrier (generation counter survives graph replays:
// count returns to 0 each use; gen increases monotonically -> deterministic).
__device__ unsigned g_bar_count = 0;
__device__ volatile unsigned g_bar_gen = 0;

// ---------------------------------------------------------------------------
// K1: LIF over T=4 + GAP over N, fused. One block per (b, c): 8192 blocks.
// 256 threads, each owns one float4 per timestep (front-batched, MLP_p1=4).
// Streaming loads (__ldcs): x is touched exactly once.
// Blocks 0..8 prefetch ALL MLP parameters into L2 (w1, w2, and the six
// small vectors) so the MLP kernel sees only L2 hits.
// ---------------------------------------------------------------------------
__global__ void __launch_bounds__(256) lif_gap_kernel(const float* __restrict__ x,
                                                      const float* __restrict__ w1,
                                                      const float* __restrict__ w2,
                                                      const float* __restrict__ b1,
                                                      const float* __restrict__ gamma1,
                                                      const float* __restrict__ beta1,
                                                      const float* __restrict__ b2,
                                                      const float* __restrict__ gamma2,
                                                      const float* __restrict__ beta2,
                                                      float* __restrict__ g) {
    const int bc  = blockIdx.x;          // 0..8191
    const int b   = bc >> 9;             // /512
    const int c   = bc & (C_ - 1);
    const int tid = threadIdx.x;

    // L2 warm-up: w1/w2 = 128 KB each (1024 lines); small vectors = 54 lines
    if (bc < 8) {
        const float* wsrc = (bc < 4) ? w1 : w2;
        const char* line = (const char*)wsrc + ((size_t)(bc & 3) * 256 + tid) * 128;
        asm volatile("prefetch.global.L2 [%0];" :: "l"(line));
    } else if (bc == 8 && tid < 54) {
        const float* p; int off;
        if (tid < 6) { p = (tid < 2) ? b1 : (tid < 4) ? gamma1 : beta1; off = tid & 1; }
        else { int u = tid - 6; p = (u < 16) ? b2 : (u < 32) ? gamma2 : beta2; off = u & 15; }
        asm volatile("prefetch.global.L2 [%0];" :: "l"((const char*)p + (size_t)off * 128));
    }

    const size_t strideT = (size_t)B_ * C_ * N_;
    const size_t base = ((size_t)b * C_ + c) * N_ + (size_t)tid * 4;

    float4 xt[T_];
#pragma unroll
    for (int t = 0; t < T_; t++)
        xt[t] = __ldcs(reinterpret_cast<const float4*>(x + base + (size_t)t * strideT));

    float sums[T_] = {0.f, 0.f, 0.f, 0.f};
#pragma unroll
    for (int slot = 0; slot < 4; slot++) {
        float v = 0.f;
#pragma unroll
        for (int t = 0; t < T_; t++) {
            float xv = (slot == 0) ? xt[t].x : (slot == 1) ? xt[t].y
                     : (slot == 2) ? xt[t].z : xt[t].w;
            v = 0.5f * (v + xv);                 // v += (x - v)/TAU, TAU=2
            float s = (v >= 1.0f) ? 1.0f : 0.0f; // spike(v - V_TH)
            sums[t] += s;
            v *= (1.0f - s);                     // hard reset (detached)
        }
    }

    __shared__ float red[8][T_];
    const int lane = tid & 31;
    const int wid  = tid >> 5;
#pragma unroll
    for (int t = 0; t < T_; t++) {
#pragma unroll
        for (int off = 16; off > 0; off >>= 1)
            sums[t] += __shfl_xor_sync(0xFFFFFFFFu, sums[t], off);
    }
    if (lane == 0) {
#pragma unroll
        for (int t = 0; t < T_; t++) red[wid][t] = sums[t];
    }
    __syncthreads();

    if (tid < T_) {
        float tot = 0.f;
#pragma unroll
        for (int w = 0; w < 8; w++) tot += red[w][tid];
        g[((tid * B_ + b) * C_) + c] = tot * (1.0f / (float)N_);
    }
}

// ---------------------------------------------------------------------------
// K2: full MLP, fused. 64 blocks x 256 threads, all co-resident.
// Round-8 proven structure + latency removal:
//   - all per-column scalars loaded at kernel entry (L2-warm)
//   - this block's 8 w2 rows staged into smem BEFORE the barrier
//   - nanosleep barrier (tight spin measured 4us slower in R9)
// ---------------------------------------------------------------------------
__global__ void __launch_bounds__(256) mlp_fused_kernel(const float* __restrict__ g,
                                                        const float* __restrict__ w1,
                                                        const float* __restrict__ b1,
                                                        const float* __restrict__ gamma1,
                                                        const float* __restrict__ beta1,
                                                        const float* __restrict__ w2,
                                                        const float* __restrict__ b2,
                                                        const float* __restrict__ gamma2,
                                                        const float* __restrict__ beta2,
                                                        float* __restrict__ h1,
                                                        float* __restrict__ out) {
    const int j   = blockIdx.x;   // 0..63
    const int tid = threadIdx.x;
    const int grp = tid >> 6;     // 0..3  (phase-2 column group)
    const int gt  = tid & 63;     // phase-2 batch row
    const int gw  = (tid >> 5) & 1;
    const int jj0 = j * 8 + grp;
    const int jj1 = j * 8 + 4 + grp;

    __shared__ float4 w1s[C_ / 4];      // 2 KB: w1 row j
    __shared__ float4 w2s[8 * 16];      // 2 KB: w2 rows j*8 .. j*8+7
    __shared__ float  hrow[TB_];
    __shared__ float  ss[4][2], sq[4][2];
    __shared__ float  ss1[4][2], sq1[4][2];

    // Early scalar loads (all L2-warm via K1 prefetch) — off critical path
    const float b1j  = b1[j];
    const float g1j  = gamma1[j];
    const float be1j = beta1[j];
    const float b20  = b2[jj0],  b21  = b2[jj1];
    const float gm20 = gamma2[jj0], gm21 = gamma2[jj1];
    const float bt20 = beta2[jj0],  bt21 = beta2[jj1];

    // Stage w1 row j and the 8 w2 rows (both coalesced, 128 threads each)
    if (tid < C_ / 4) {
        w1s[tid] = reinterpret_cast<const float4*>(w1 + (size_t)j * C_)[tid];
    } else {
        const int m = tid - C_ / 4;     // 0..127 -> 8 rows x 16 float4
        w2s[m] = reinterpret_cast<const float4*>(w2)[(size_t)j * 128 + m];
    }
    __syncthreads();

    // ---------------- Phase 1: h1[:, j] = BN1(g @ w1[j,:] + b1[j]) ----------
    {
        const int w = tid >> 5, l = tid & 31;
#pragma unroll
        for (int r = 0; r < 8; r++) {
            const int i = w * 8 + r;                       // batch row 0..63
            const float4* gr = reinterpret_cast<const float4*>(g + (size_t)i * C_);
            float acc = 0.f;
#pragma unroll
            for (int s = 0; s < 4; s++) {                  // 32-lane coalesced
                float4 a = gr[l + s * 32], wv = w1s[l + s * 32];
                acc += a.x * wv.x + a.y * wv.y + a.z * wv.z + a.w * wv.w;
            }
#pragma unroll
            for (int off = 16; off > 0; off >>= 1)
                acc += __shfl_xor_sync(0xFFFFFFFFu, acc, off);
            if (l == 0) hrow[i] = acc + b1j;
        }
    }
    __syncthreads();

    if (tid < TB_) {
        float h = hrow[tid];
        float s = h, q = h * h;
#pragma unroll
        for (int off = 16; off > 0; off >>= 1) {
            s += __shfl_xor_sync(0xFFFFFFFFu, s, off);
            q += __shfl_xor_sync(0xFFFFFFFFu, q, off);
        }
        if ((tid & 31) == 0) { ss[0][tid >> 5] = s; sq[0][tid >> 5] = q; }
    }
    __syncthreads();
    if (tid < TB_) {
        float mu  = (ss[0][0] + ss[0][1]) * (1.0f / (float)TB_);
        float ex2 = (sq[0][0] + sq[0][1]) * (1.0f / (float)TB_);
        float var = ex2 - mu * mu;
        h1[tid * CR_ + j] = (hrow[tid] - mu) * rsqrtf(var + BN_EPS) * g1j + be1j;
    }
    __syncthreads();

    // ---------------- Grid barrier (64 co-resident blocks) ------------------
    if (tid == 0) {
        __threadfence();                               // publish h1
        unsigned gen = g_bar_gen;
        unsigned old = atomicAdd(&g_bar_count, 1);
        if (old == (unsigned)(gridDim.x - 1)) {
            g_bar_count = 0;
            __threadfence();
            g_bar_gen = gen + 1;                       // release
        } else {
            while (g_bar_gen == gen) __nanosleep(40);
        }
    }
    __syncthreads();
    __threadfence();                                   // acquire h1

    // ---------------- Phase 2: out[:, j*8 .. j*8+7] --------------------------
    {
        const float4* hr = reinterpret_cast<const float4*>(h1 + (size_t)gt * CR_);
        const int rr0 = grp, rr1 = 4 + grp;            // rows within w2s

        float a00=0.f, a01=0.f, a02=0.f, a03=0.f;
        float a10=0.f, a11=0.f, a12=0.f, a13=0.f;
#pragma unroll
        for (int k = 0; k < CR_ / 16; k++) {
            float4 x0 = hr[k*4+0], x1 = hr[k*4+1], x2 = hr[k*4+2], x3 = hr[k*4+3];
            float4 u0 = w2s[rr0*16 + k*4+0], u1 = w2s[rr0*16 + k*4+1];
            float4 u2 = w2s[rr0*16 + k*4+2], u3 = w2s[rr0*16 + k*4+3];
            float4 v0 = w2s[rr1*16 + k*4+0], v1 = w2s[rr1*16 + k*4+1];
            float4 v2 = w2s[rr1*16 + k*4+2], v3 = w2s[rr1*16 + k*4+3];
            a00 += x0.x*u0.x + x0.y*u0.y + x0.z*u0.z + x0.w*u0.w;
            a01 += x1.x*u1.x + x1.y*u1.y + x1.z*u1.z + x1.w*u1.w;
            a02 += x2.x*u2.x + x2.y*u2.y + x2.z*u2.z + x2.w*u2.w;
            a03 += x3.x*u3.x + x3.y*u3.y + x3.z*u3.z + x3.w*u3.w;
            a10 += x0.x*v0.x + x0.y*v0.y + x0.z*v0.z + x0.w*v0.w;
            a11 += x1.x*v1.x + x1.y*v1.y + x1.z*v1.z + x1.w*v1.w;
            a12 += x2.x*v2.x + x2.y*v2.y + x2.z*v2.z + x2.w*v2.w;
            a13 += x3.x*v3.x + x3.y*v3.y + x3.z*v3.z + x3.w*v3.w;
        }
        float h0 = (a00 + a01) + (a02 + a03) + b20;
        float h1v = (a10 + a11) + (a12 + a13) + b21;

        // Two interleaved stat reductions over the 64-thread group
        float s0 = h0, q0 = h0 * h0, s1 = h1v, q1 = h1v * h1v;
#pragma unroll
        for (int off = 16; off > 0; off >>= 1) {
            s0 += __shfl_xor_sync(0xFFFFFFFFu, s0, off);
            q0 += __shfl_xor_sync(0xFFFFFFFFu, q0, off);
            s1 += __shfl_xor_sync(0xFFFFFFFFu, s1, off);
            q1 += __shfl_xor_sync(0xFFFFFFFFu, q1, off);
        }
        if ((gt & 31) == 0) {
            ss[grp][gw] = s0;  sq[grp][gw] = q0;
            ss1[grp][gw] = s1; sq1[grp][gw] = q1;
        }
        __syncthreads();
        {
            float mu  = (ss[grp][0] + ss[grp][1]) * (1.0f / (float)TB_);
            float ex2 = (sq[grp][0] + sq[grp][1]) * (1.0f / (float)TB_);
            float var = ex2 - mu * mu;
            out[gt * C_ + jj0] = (h0 - mu) * rsqrtf(var + BN_EPS) * gm20 + bt20;
        }
        {
            float mu  = (ss1[grp][0] + ss1[grp][1]) * (1.0f / (float)TB_);
            float ex2 = (sq1[grp][0] + sq1[grp][1]) * (1.0f / (float)TB_);
            float var = ex2 - mu * mu;
            out[gt * C_ + jj1] = (h1v - mu) * rsqrtf(var + BN_EPS) * gm21 + bt21;
        }
    }
}

// ---------------------------------------------------------------------------
extern "C" void kernel_launch(void* const* d_in, const int* in_sizes, int n_in,
                              void* d_out, int out_size) {
    const float* x      = (const float*)d_in[0];
    const float* w1     = (const float*)d_in[1];
    const float* b1     = (const float*)d_in[2];
    const float* gamma1 = (const float*)d_in[3];
    const float* beta1  = (const float*)d_in[4];
    const float* w2     = (const float*)d_in[5];
    const float* b2     = (const float*)d_in[6];
    const float* gamma2 = (const float*)d_in[7];
    const float* beta2  = (const float*)d_in[8];
    float* out = (float*)d_out;

    float* g;  cudaGetSymbolAddress((void**)&g,  g_gap);
    float* h1; cudaGetSymbolAddress((void**)&h1, g_h1);

    lif_gap_kernel<<<B_ * C_, 256>>>(x, w1, w2, b1, gamma1, beta1,
                                     b2, gamma2, beta2, g);
    mlp_fused_kernel<<<CR_, 256>>>(g, w1, b1, gamma1, beta1,
                                   w2, b2, gamma2, beta2, h1, out);
}

// round 11
// speedup vs baseline: 1.0626x; 1.0029x over previous
#include <cuda_runtime.h>

// Problem constants
#define T_  4
#define B_  16
#define C_  512
#define N_  1024
#define CR_ 64
#define TB_ (T_ * B_)          // 64
#define BN_EPS 1e-5f

// Scratch (allocation-free rule: __device__ globals)
__device__ float g_gap[TB_ * C_];   // [64, 512]
__device__ float g_h1[TB_ * CR_];   // [64, 64]

// Software grid barrier (generation counter survives graph replays)
__device__ unsigned g_bar_count = 0;
__device__ volatile unsigned g_bar_gen = 0;

// ---------------------------------------------------------------------------
// K1: LIF over T=4 + GAP over N. One block per (b, c): 8192 blocks.
// The LAST 16 blocks (which run in the final wave) prefetch w1, w2, g and the
// small parameter vectors into L2 so they are RESIDENT when K2 launches
// (prefetching at K1 start is useless: the 128 MiB x stream evicts them).
// ---------------------------------------------------------------------------
__global__ void __launch_bounds__(256) lif_gap_kernel(const float* __restrict__ x,
                                                      const float* __restrict__ w1,
                                                      const float* __restrict__ w2,
                                                      const float* __restrict__ b1,
                                                      const float* __restrict__ gamma1,
                                                      const float* __restrict__ beta1,
                                                      const float* __restrict__ b2,
                                                      const float* __restrict__ gamma2,
                                                      const float* __restrict__ beta2,
                                                      float* __restrict__ g) {
    const int bc  = blockIdx.x;          // 0..8191
    const int b   = bc >> 9;             // /512
    const int c   = bc & (C_ - 1);
    const int tid = threadIdx.x;

    const size_t strideT = (size_t)B_ * C_ * N_;
    const size_t base = ((size_t)b * C_ + c) * N_ + (size_t)tid * 4;

    float4 xt[T_];
#pragma unroll
    for (int t = 0; t < T_; t++)
        xt[t] = __ldcs(reinterpret_cast<const float4*>(x + base + (size_t)t * strideT));

    float sums[T_] = {0.f, 0.f, 0.f, 0.f};
#pragma unroll
    for (int slot = 0; slot < 4; slot++) {
        float v = 0.f;
#pragma unroll
        for (int t = 0; t < T_; t++) {
            float xv = (slot == 0) ? xt[t].x : (slot == 1) ? xt[t].y
                     : (slot == 2) ? xt[t].z : xt[t].w;
            v = 0.5f * (v + xv);                 // v += (x - v)/TAU, TAU=2
            float s = (v >= 1.0f) ? 1.0f : 0.0f; // spike(v - V_TH)
            sums[t] += s;
            v *= (1.0f - s);                     // hard reset (detached)
        }
    }

    __shared__ float red[8][T_];
    const int lane = tid & 31;
    const int wid  = tid >> 5;
#pragma unroll
    for (int t = 0; t < T_; t++) {
#pragma unroll
        for (int off = 16; off > 0; off >>= 1)
            sums[t] += __shfl_xor_sync(0xFFFFFFFFu, sums[t], off);
    }
    if (lane == 0) {
#pragma unroll
        for (int t = 0; t < T_; t++) red[wid][t] = sums[t];
    }
    __syncthreads();

    if (tid < T_) {
        float tot = 0.f;
#pragma unroll
        for (int w = 0; w < 8; w++) tot += red[w][tid];
        g[((tid * B_ + b) * C_) + c] = tot * (1.0f / (float)N_);
    }

    // Late L2 warm-up by the final-wave blocks (survives until K2).
    // w1: 1024 lines, w2: 1024, g: 1024, small vectors: 54.
    if (bc >= 8176) {
        const int id = bc - 8176;        // 0..15
        if (id < 4) {
            const char* p = (const char*)w1 + ((size_t)id * 256 + tid) * 128;
            asm volatile("prefetch.global.L2 [%0];" :: "l"(p));
        } else if (id < 8) {
            const char* p = (const char*)w2 + ((size_t)(id - 4) * 256 + tid) * 128;
            asm volatile("prefetch.global.L2 [%0];" :: "l"(p));
        } else if (id < 12) {
            const char* p = (const char*)g + ((size_t)(id - 8) * 256 + tid) * 128;
            asm volatile("prefetch.global.L2 [%0];" :: "l"(p));
        } else if (id == 12 && tid < 54) {
            const float* p; int off;
            if (tid < 6) { p = (tid < 2) ? b1 : (tid < 4) ? gamma1 : beta1; off = tid & 1; }
            else { int u = tid - 6; p = (u < 16) ? b2 : (u < 32) ? gamma2 : beta2; off = u & 15; }
            asm volatile("prefetch.global.L2 [%0];" :: "l"((const char*)p + (size_t)off * 128));
        }
    }
}

// ---------------------------------------------------------------------------
// K2: full MLP, fused. 64 blocks x 256 threads, all co-resident (1 block/SM,
// so register pressure is irrelevant — we SPEND registers to buy MLP).
// Phase 1: ALL 32 g-loads per warp buffered in registers before any compute
//          -> one memory-latency exposure instead of 8 serialized rounds.
// Grid barrier (nanosleep poll).
// Phase 2: w2 rows pre-staged in smem before the barrier; h1 loads buffered.
// ---------------------------------------------------------------------------
__global__ void __launch_bounds__(256) mlp_fused_kernel(const float* __restrict__ g,
                                                        const float* __restrict__ w1,
                                                        const float* __restrict__ b1,
                                                        const float* __restrict__ gamma1,
                                                        const float* __restrict__ beta1,
                                                        const float* __restrict__ w2,
                                                        const float* __restrict__ b2,
                                                        const float* __restrict__ gamma2,
                                                        const float* __restrict__ beta2,
                                                        float* __restrict__ h1,
                                                        float* __restrict__ out) {
    const int j   = blockIdx.x;   // 0..63
    const int tid = threadIdx.x;
    const int grp = tid >> 6;     // 0..3  (phase-2 column group)
    const int gt  = tid & 63;     // phase-2 batch row
    const int gw  = (tid >> 5) & 1;
    const int jj0 = j * 8 + grp;
    const int jj1 = j * 8 + 4 + grp;

    __shared__ float4 w1s[C_ / 4];      // 2 KB: w1 row j
    __shared__ float4 w2s[8 * 16];      // 2 KB: w2 rows j*8 .. j*8+7
    __shared__ float  hrow[TB_];
    __shared__ float  ss[4][2], sq[4][2];
    __shared__ float  ss1[4][2], sq1[4][2];

    // Early scalar loads (L2-warm) — issued at entry, consumed late
    const float b1j  = b1[j];
    const float g1j  = gamma1[j];
    const float be1j = beta1[j];
    const float b20  = b2[jj0],  b21  = b2[jj1];
    const float gm20 = gamma2[jj0], gm21 = gamma2[jj1];
    const float bt20 = beta2[jj0],  bt21 = beta2[jj1];

    // Stage w1 row j and this block's 8 w2 rows (coalesced)
    if (tid < C_ / 4) {
        w1s[tid] = reinterpret_cast<const float4*>(w1 + (size_t)j * C_)[tid];
    } else {
        const int m = tid - C_ / 4;     // 0..127 -> 8 rows x 16 float4
        w2s[m] = reinterpret_cast<const float4*>(w2)[(size_t)j * 128 + m];
    }

    // ---------------- Phase 1: h1[:, j] = BN1(g @ w1[j,:] + b1[j]) ----------
    // Issue ALL 32 independent g-loads before any compute.
    const int w = tid >> 5, l = tid & 31;
    float4 abuf[4][8];                   // [chunk][row] = 128 registers
    {
        const float4* g4 = reinterpret_cast<const float4*>(g);
#pragma unroll
        for (int s = 0; s < 4; s++)
#pragma unroll
            for (int r = 0; r < 8; r++)
                abuf[s][r] = g4[(size_t)(w * 8 + r) * (C_ / 4) + l + s * 32];
    }
    __syncthreads();                     // w1s ready (loads above already in flight)

    {
        float acc[8] = {0.f,0.f,0.f,0.f,0.f,0.f,0.f,0.f};
#pragma unroll
        for (int s = 0; s < 4; s++) {
            float4 wv = w1s[l + s * 32];
#pragma unroll
            for (int r = 0; r < 8; r++) {
                float4 a = abuf[s][r];
                acc[r] += a.x * wv.x + a.y * wv.y + a.z * wv.z + a.w * wv.w;
            }
        }
        // 8 interleaved shuffle-reduce chains (independent -> latency hidden)
#pragma unroll
        for (int off = 16; off > 0; off >>= 1)
#pragma unroll
            for (int r = 0; r < 8; r++)
                acc[r] += __shfl_xor_sync(0xFFFFFFFFu, acc[r], off);
        if (l == 0) {
#pragma unroll
            for (int r = 0; r < 8; r++) hrow[w * 8 + r] = acc[r] + b1j;
        }
    }
    __syncthreads();

    // BN1 column stats (64 values, 2 warps)
    if (tid < TB_) {
        float h = hrow[tid];
        float s = h, q = h * h;
#pragma unroll
        for (int off = 16; off > 0; off >>= 1) {
            s += __shfl_xor_sync(0xFFFFFFFFu, s, off);
            q += __shfl_xor_sync(0xFFFFFFFFu, q, off);
        }
        if ((tid & 31) == 0) { ss[0][tid >> 5] = s; sq[0][tid >> 5] = q; }
    }
    __syncthreads();
    if (tid < TB_) {
        float mu  = (ss[0][0] + ss[0][1]) * (1.0f / (float)TB_);
        float ex2 = (sq[0][0] + sq[0][1]) * (1.0f / (float)TB_);
        float var = ex2 - mu * mu;
        h1[tid * CR_ + j] = (hrow[tid] - mu) * rsqrtf(var + BN_EPS) * g1j + be1j;
    }
    __syncthreads();

    // ---------------- Grid barrier (64 co-resident blocks) ------------------
    if (tid == 0) {
        __threadfence();                               // publish h1
        unsigned gen = g_bar_gen;
        unsigned old = atomicAdd(&g_bar_count, 1);
        if (old == (unsigned)(gridDim.x - 1)) {
            g_bar_count = 0;
            __threadfence();
            g_bar_gen = gen + 1;                       // release
        } else {
            while (g_bar_gen == gen) __nanosleep(40);
        }
    }
    __syncthreads();
    __threadfence();                                   // acquire h1

    // ---------------- Phase 2: out[:, j*8 .. j*8+7] --------------------------
    {
        // Buffer the full h1 row (16 float4) before any compute
        const float4* hr = reinterpret_cast<const float4*>(h1 + (size_t)gt * CR_);
        float4 hbuf[16];
#pragma unroll
        for (int k = 0; k < 16; k++) hbuf[k] = hr[k];

        const int rr0 = grp, rr1 = 4 + grp;
        float a00=0.f, a01=0.f, a02=0.f, a03=0.f;
        float a10=0.f, a11=0.f, a12=0.f, a13=0.f;
#pragma unroll
        for (int k = 0; k < CR_ / 16; k++) {
            float4 x0 = hbuf[k*4+0], x1 = hbuf[k*4+1], x2 = hbuf[k*4+2], x3 = hbuf[k*4+3];
            float4 u0 = w2s[rr0*16 + k*4+0], u1 = w2s[rr0*16 + k*4+1];
            float4 u2 = w2s[rr0*16 + k*4+2], u3 = w2s[rr0*16 + k*4+3];
            float4 v0 = w2s[rr1*16 + k*4+0], v1 = w2s[rr1*16 + k*4+1];
            float4 v2 = w2s[rr1*16 + k*4+2], v3 = w2s[rr1*16 + k*4+3];
            a00 += x0.x*u0.x + x0.y*u0.y + x0.z*u0.z + x0.w*u0.w;
            a01 += x1.x*u1.x + x1.y*u1.y + x1.z*u1.z + x1.w*u1.w;
            a02 += x2.x*u2.x + x2.y*u2.y + x2.z*u2.z + x2.w*u2.w;
            a03 += x3.x*u3.x + x3.y*u3.y + x3.z*u3.z + x3.w*u3.w;
            a10 += x0.x*v0.x + x0.y*v0.y + x0.z*v0.z + x0.w*v0.w;
            a11 += x1.x*v1.x + x1.y*v1.y + x1.z*v1.z + x1.w*v1.w;
            a12 += x2.x*v2.x + x2.y*v2.y + x2.z*v2.z + x2.w*v2.w;
            a13 += x3.x*v3.x + x3.y*v3.y + x3.z*v3.z + x3.w*v3.w;
        }
        float h0 = (a00 + a01) + (a02 + a03) + b20;
        float h1v = (a10 + a11) + (a12 + a13) + b21;

        float s0 = h0, q0 = h0 * h0, s1 = h1v, q1 = h1v * h1v;
#pragma unroll
        for (int off = 16; off > 0; off >>= 1) {
            s0 += __shfl_xor_sync(0xFFFFFFFFu, s0, off);
            q0 += __shfl_xor_sync(0xFFFFFFFFu, q0, off);
            s1 += __shfl_xor_sync(0xFFFFFFFFu, s1, off);
            q1 += __shfl_xor_sync(0xFFFFFFFFu, q1, off);
        }
        if ((gt & 31) == 0) {
            ss[grp][gw] = s0;  sq[grp][gw] = q0;
            ss1[grp][gw] = s1; sq1[grp][gw] = q1;
        }
        __syncthreads();
        {
            float mu  = (ss[grp][0] + ss[grp][1]) * (1.0f / (float)TB_);
            float ex2 = (sq[grp][0] + sq[grp][1]) * (1.0f / (float)TB_);
            float var = ex2 - mu * mu;
            out[gt * C_ + jj0] = (h0 - mu) * rsqrtf(var + BN_EPS) * gm20 + bt20;
        }
        {
            float mu  = (ss1[grp][0] + ss1[grp][1]) * (1.0f / (float)TB_);
            float ex2 = (sq1[grp][0] + sq1[grp][1]) * (1.0f / (float)TB_);
            float var = ex2 - mu * mu;
            out[gt * C_ + jj1] = (h1v - mu) * rsqrtf(var + BN_EPS) * gm21 + bt21;
        }
    }
}

// ---------------------------------------------------------------------------
extern "C" void kernel_launch(void* const* d_in, const int* in_sizes, int n_in,
                              void* d_out, int out_size) {
    const float* x      = (const float*)d_in[0];
    const float* w1     = (const float*)d_in[1];
    const float* b1     = (const float*)d_in[2];
    const float* gamma1 = (const float*)d_in[3];
    const float* beta1  = (const float*)d_in[4];
    const float* w2     = (const float*)d_in[5];
    const float* b2     = (const float*)d_in[6];
    const float* gamma2 = (const float*)d_in[7];
    const float* beta2  = (const float*)d_in[8];
    float* out = (float*)d_out;

    float* g;  cudaGetSymbolAddress((void**)&g,  g_gap);
    float* h1; cudaGetSymbolAddress((void**)&h1, g_h1);

    lif_gap_kernel<<<B_ * C_, 256>>>(x, w1, w2, b1, gamma1, beta1,
                                     b2, gamma2, beta2, g);
    mlp_fused_kernel<<<CR_, 256>>>(g, w1, b1, gamma1, beta1,
                                   w2, b2, gamma2, beta2, h1, out);
}